// round 16
// baseline (speedup 1.0000x reference)
#include <cuda_runtime.h>
#include <math.h>

// Fixed problem shapes
#define BB    8
#define NA    5
#define NC    8
#define NH    192
#define NW    192
#define TT    50
#define ATTRS 15                 // 7 + NC
#define NHW   (NH*NW)            // 36864
#define CELLS (BB*NA*NHW)        // 1,474,560

#define TPB       256
#define CPT       8
#define NB_SPARSE BB                      // one block per batch
#define NB_DENSE  (CELLS/(CPT*TPB))       // 720 (exact)
#define NB_TOTAL  (NB_SPARSE+NB_DENSE)    // 728
#define NWARP     (TPB/32)                // 8
#define TICKETS   (NB_TOTAL*NWARP)        // 5824 warp tickets
#define HASH_SZ   512
#define HASH_MASK (HASH_SZ-1)

// ---- persistent device scratch (finisher resets -> replay-safe) ----
__device__ float    g_S0 = 0.f;
__device__ float    g_crA[7];            // 0:noobjCorr 1:objconf 2..5:coords 6:ce
__device__ int      g_nObjG, g_removedG;
__device__ unsigned g_ticket = 0;

__device__ __forceinline__ float sp_fast(float v) {   // softplus == bce0 (clip never binds, |v|<16)
    return fmaxf(v, 0.f) + __logf(1.f + __expf(-fabsf(v)));
}
__device__ __forceinline__ float sigf(float v) {
    return 1.f / (1.f + __expf(-v));
}
__device__ __forceinline__ unsigned hash_cell(int cell) {
    return (((unsigned)cell * 2654435761u) >> 16) & HASH_MASK;
}

__device__ __forceinline__ void warp_ticket(float* out) {
    __threadfence();
    unsigned old = atomicAdd(&g_ticket, 1u);
    if (old == (unsigned)(TICKETS - 1)) {
        double S0   = (double)*(volatile float*)&g_S0 + (double)*(volatile float*)&g_crA[0];
        double nobj = (double)*(volatile int*)&g_nObjG;
        double cnt  = (double)CELLS - (double)*(volatile int*)&g_removedG;
        double objs = (double)*(volatile float*)&g_crA[2] + (double)*(volatile float*)&g_crA[3]
                    + (double)*(volatile float*)&g_crA[4] + (double)*(volatile float*)&g_crA[5]
                    + (double)*(volatile float*)&g_crA[1]
                    + (double)*(volatile float*)&g_crA[6] / (double)BB;
        out[0] = (float)(objs / nobj + S0 / cnt);
        // replay-safe resets
        g_S0 = 0.f;
        g_ticket = 0u;
        #pragma unroll
        for (int i = 0; i < 7; i++) g_crA[i] = 0.f;
        g_nObjG = 0; g_removedG = 0;
    }
}

__global__ void __launch_bounds__(TPB)
fused(const float* __restrict__ x,
      const float* __restrict__ tg,
      const float* __restrict__ anchors,
      float* __restrict__ out)
{
    // sparse-only shared (~2.5KB; dense path never touches shared)
    __shared__ int   s_hash[HASH_SZ];
    __shared__ int   s_meta[TT];
    __shared__ unsigned char s_loser[TT];
    __shared__ float s_gw[TT], s_gh[TT];
    __shared__ float s_anchor[2*NA];

    const int tid  = threadIdx.x;
    const int bid  = blockIdx.x;
    const int lane = tid & 31;

    if (bid >= NB_SPARSE) {
        // ========== dense: 8 cells/thread, MLP=2, warp-autonomous ==========
        int c0 = ((bid - NB_SPARSE) * TPB + tid) * CPT;
        int ba = c0 / NHW;                        // 8 cells never cross ba (NHW%8==0)
        const float* p = x + (size_t)c0 + (size_t)(6 + 14 * ba) * NHW;
        float4 A = *(const float4*)p;
        float4 B = *(const float4*)(p + 4);       // 2 independent LDG.128
        float local = (sp_fast(A.x) + sp_fast(A.y)) + (sp_fast(A.z) + sp_fast(A.w))
                    + (sp_fast(B.x) + sp_fast(B.y)) + (sp_fast(B.z) + sp_fast(B.w));

        #pragma unroll
        for (int o = 16; o; o >>= 1) local += __shfl_down_sync(0xffffffffu, local, o);
        if (lane == 0) {
            atomicAdd(&g_S0, local);              // REDG.F32 per warp
            warp_ticket(out);
        }
        // no __syncthreads, no shared in dense path
    } else {
        // ========== sparse: one block per batch ==========
        const int b = bid;
        float a0 = 0.f, a1 = 0.f, a2 = 0.f, a3 = 0.f, a4 = 0.f, a5 = 0.f, a6 = 0.f;
        float r_fx = 0.f, r_fy = 0.f, r_tw = 0.f, r_th = 0.f;
        int   r_label = 0;

        for (int i = tid; i < HASH_SZ; i += TPB) s_hash[i] = -1;
        if (tid < TT) s_loser[tid] = 0;
        if (tid < 2*NA) s_anchor[tid] = anchors[tid];
        __syncthreads();

        // phase 0: one thread per target
        if (tid < TT) {
            const int t = b * TT + tid;
            const float* r = tg + (size_t)t * 5;
            float r0 = r[0], r1 = r[1], r2 = r[2], r3 = r[3], r4 = r[4];
            int valid = ((r0 + r1 + r2 + r3 + r4) != 0.f);
            float gx = r1 * NW, gy = r2 * NH, gw = r3 * NW, gh = r4 * NH;
            int gi = (int)floorf(gx), gj = (int)floorf(gy);
            float bestIou = -1.f; int best = 0; float awb = 1.f, ahb = 1.f;
            #pragma unroll
            for (int a = 0; a < NA; a++) {
                float aw = s_anchor[2*a], ah = s_anchor[2*a+1];
                float inter = fminf(gw, aw) * fminf(gh, ah);
                float iou   = inter / (gw * gh + aw * ah - inter);
                if (iou > bestIou) { bestIou = iou; best = a; awb = aw; ahb = ah; }
            }
            s_meta[tid] = (valid << 28) | (best << 16) | (gj << 8) | gi;
            s_gw[tid] = gw; s_gh[tid] = gh;
            r_label = (int)r0;
            r_fx = gx - floorf(gx);
            r_fy = gy - floorf(gy);
            r_tw = __logf(gw / awb + 1e-16f);
            r_th = __logf(gh / ahb + 1e-16f);
        }
        __syncthreads();

        // phase 0.5: last-write-wins within this batch (2500 pairs)
        for (int p = tid; p < TT*TT; p += TPB) {
            int ti = p / TT, tj = p - (p / TT) * TT;
            if (tj > ti) {
                int m1 = s_meta[ti];
                if ((m1 >> 28) && m1 == s_meta[tj]) s_loser[ti] = 1;   // benign race
            }
        }
        __syncthreads();

        // phase 1+2 merged: union correction is order-free (same -bce0 either way)
        if (tid < TT) {
            int meta = s_meta[tid];
            if ((meta >> 28) && !s_loser[tid]) {
                int best = (meta >> 16) & 0xff, gj = (meta >> 8) & 0xff, gi = meta & 0xff;
                int cell = ((b * NA + best) * NH + gj) * NW + gi;
                unsigned h = hash_cell(cell);
                bool mine = false;
                while (true) {
                    int prev = atomicCAS(&s_hash[h], -1, cell);
                    if (prev == -1)   { mine = true; break; }
                    if (prev == cell) break;
                    h = (h + 1) & HASH_MASK;
                }
                atomicAdd(&g_nObjG, 1);             // REDG.S32, no-return

                const float* bp = x + (size_t)(b * NA + best) * ATTRS * NHW
                                    + (size_t)gj * NW + gi;
                float x0 = bp[0];
                float x1 = bp[(size_t)NHW];
                float x2 = bp[2 * (size_t)NHW];
                float x3 = bp[3 * (size_t)NHW];
                float xc = bp[6 * (size_t)NHW];
                float sv[NC];
                #pragma unroll
                for (int c = 0; c < NC; c++) sv[c] = bp[(size_t)(7 + c) * NHW];

                float dx = sigf(x0) - r_fx;
                float dy = sigf(x1) - r_fy;
                float dw = x2 - r_tw;
                float dh = x3 - r_th;
                a2 += dx * dx;
                a3 += dy * dy;
                a4 += dw * dw;
                a5 += dh * dh;
                a1 += sp_fast(-xc);
                if (mine) { a0 -= sp_fast(xc); atomicAdd(&g_removedG, 1); }

                float m = -1e30f;
                #pragma unroll
                for (int c = 0; c < NC; c++) { sv[c] = sigf(sv[c]); m = fmaxf(m, sv[c]); }
                float sum = 0.f;
                #pragma unroll
                for (int c = 0; c < NC; c++) sum += __expf(sv[c] - m);
                a6 += m + __logf(sum) - sv[r_label];
            }
        }
        if (tid < TT * NA) {                        // 250 ignore candidates
            int tl = tid / NA, a = tid - (tid / NA) * NA;
            int meta = s_meta[tl];
            if (meta >> 28) {
                float gw = s_gw[tl], gh = s_gh[tl];
                float aw = s_anchor[2*a], ah = s_anchor[2*a+1];
                float inter = fminf(gw, aw) * fminf(gh, ah);
                float iou   = inter / (gw * gh + aw * ah - inter);
                if (iou > 0.6f) {
                    int gj = (meta >> 8) & 0xff, gi = meta & 0xff;
                    int cell = ((b * NA + a) * NH + gj) * NW + gi;
                    unsigned h = hash_cell(cell);
                    bool mine = false;
                    while (true) {
                        int prev = atomicCAS(&s_hash[h], -1, cell);
                        if (prev == -1)   { mine = true; break; }
                        if (prev == cell) break;       // claimed (obj or dup)
                        h = (h + 1) & HASH_MASK;
                    }
                    if (mine) {
                        atomicAdd(&g_removedG, 1);
                        float xc = x[((size_t)(b * NA + a) * ATTRS + 6) * NHW
                                     + (size_t)gj * NW + gi];
                        a0 -= sp_fast(xc);
                    }
                }
            }
        }

        // warp-autonomous tail: shuffle-reduce 7 floats, lane0 posts REDG.F32 x7
        #pragma unroll
        for (int o = 16; o; o >>= 1) {
            a0 += __shfl_down_sync(0xffffffffu, a0, o);
            a1 += __shfl_down_sync(0xffffffffu, a1, o);
            a2 += __shfl_down_sync(0xffffffffu, a2, o);
            a3 += __shfl_down_sync(0xffffffffu, a3, o);
            a4 += __shfl_down_sync(0xffffffffu, a4, o);
            a5 += __shfl_down_sync(0xffffffffu, a5, o);
            a6 += __shfl_down_sync(0xffffffffu, a6, o);
        }
        if (lane == 0) {
            if (a0 != 0.f) atomicAdd(&g_crA[0], a0);
            if (a1 != 0.f) atomicAdd(&g_crA[1], a1);
            if (a2 != 0.f) atomicAdd(&g_crA[2], a2);
            if (a3 != 0.f) atomicAdd(&g_crA[3], a3);
            if (a4 != 0.f) atomicAdd(&g_crA[4], a4);
            if (a5 != 0.f) atomicAdd(&g_crA[5], a5);
            if (a6 != 0.f) atomicAdd(&g_crA[6], a6);
            warp_ticket(out);
        }
    }
}

extern "C" void kernel_launch(void* const* d_in, const int* in_sizes, int n_in,
                              void* d_out, int out_size) {
    const float* x  = (const float*)d_in[0];
    const float* tg = (const float*)d_in[1];
    const float* an = (const float*)d_in[2];
    fused<<<NB_TOTAL, TPB>>>(x, tg, an, (float*)d_out);
}

// round 17
// speedup vs baseline: 1.4706x; 1.4706x over previous
#include <cuda_runtime.h>
#include <math.h>

// Fixed problem shapes
#define BB    8
#define NA    5
#define NC    8
#define NH    192
#define NW    192
#define TT    50
#define ATTRS 15                 // 7 + NC
#define NHW   (NH*NW)            // 36864
#define CELLS (BB*NA*NHW)        // 1,474,560

#define TPB       256
#define CPT       16
#define NB_SPARSE BB                      // one block per batch
#define NB_DENSE  (CELLS/(CPT*TPB))       // 360 (exact)
#define NB_TOTAL  (NB_SPARSE+NB_DENSE)    // 368
#define NWARP     (TPB/32)                // 8
#define HASH_SZ   512
#define HASH_MASK (HASH_SZ-1)

// ---- persistent device scratch (finisher resets -> replay-safe) ----
__device__ float    g_S0 = 0.f;
__device__ float    g_crA[7];            // 0:noobjCorr 1:objconf 2..5:coords 6:ce
__device__ int      g_nObjG, g_removedG;
__device__ unsigned g_ticket = 0;

__device__ __forceinline__ float sp_fast(float v) {   // softplus == bce0 (clip never binds, |v|<16)
    return fmaxf(v, 0.f) + __logf(1.f + __expf(-fabsf(v)));
}
__device__ __forceinline__ float sigf(float v) {
    return 1.f / (1.f + __expf(-v));
}
__device__ __forceinline__ unsigned hash_cell(int cell) {
    return (((unsigned)cell * 2654435761u) >> 16) & HASH_MASK;
}

__device__ __forceinline__ void block_ticket(float* out) {
    __threadfence();
    unsigned old = atomicAdd(&g_ticket, 1u);
    if (old == (unsigned)(NB_TOTAL - 1)) {
        double S0   = (double)*(volatile float*)&g_S0 + (double)*(volatile float*)&g_crA[0];
        double nobj = (double)*(volatile int*)&g_nObjG;
        double cnt  = (double)CELLS - (double)*(volatile int*)&g_removedG;
        double objs = (double)*(volatile float*)&g_crA[2] + (double)*(volatile float*)&g_crA[3]
                    + (double)*(volatile float*)&g_crA[4] + (double)*(volatile float*)&g_crA[5]
                    + (double)*(volatile float*)&g_crA[1]
                    + (double)*(volatile float*)&g_crA[6] / (double)BB;
        out[0] = (float)(objs / nobj + S0 / cnt);
        // replay-safe resets
        g_S0 = 0.f;
        g_ticket = 0u;
        #pragma unroll
        for (int i = 0; i < 7; i++) g_crA[i] = 0.f;
        g_nObjG = 0; g_removedG = 0;
    }
}

__global__ void __launch_bounds__(TPB)
fused(const float* __restrict__ x,
      const float* __restrict__ tg,
      const float* __restrict__ anchors,
      float* __restrict__ out)
{
    // shared: tiny for dense (s_red), ~3KB total for sparse
    __shared__ float s_red[NWARP][8];
    __shared__ int   s_hash[HASH_SZ];
    __shared__ int   s_meta[TT];
    __shared__ unsigned char s_loser[TT];
    __shared__ float s_gw[TT], s_gh[TT];
    __shared__ int   s_cnt[2];
    __shared__ float s_anchor[2*NA];

    const int tid  = threadIdx.x;
    const int bid  = blockIdx.x;
    const int lane = tid & 31;
    const int wid  = tid >> 5;

    if (bid >= NB_SPARSE) {
        // ========== dense: 16 cells/thread, MLP=4, block-level tail ==========
        int c0 = ((bid - NB_SPARSE) * TPB + tid) * CPT;
        int ba = c0 / NHW;                        // 16 cells never cross ba (NHW%16==0)
        const float* p = x + (size_t)c0 + (size_t)(6 + 14 * ba) * NHW;
        float4 A = *(const float4*)p;
        float4 B = *(const float4*)(p + 4);
        float4 C = *(const float4*)(p + 8);
        float4 D = *(const float4*)(p + 12);      // 4 independent LDG.128
        float local = (sp_fast(A.x) + sp_fast(A.y)) + (sp_fast(A.z) + sp_fast(A.w))
                    + (sp_fast(B.x) + sp_fast(B.y)) + (sp_fast(B.z) + sp_fast(B.w))
                    + (sp_fast(C.x) + sp_fast(C.y)) + (sp_fast(C.z) + sp_fast(C.w))
                    + (sp_fast(D.x) + sp_fast(D.y)) + (sp_fast(D.z) + sp_fast(D.w));

        #pragma unroll
        for (int o = 16; o; o >>= 1) local += __shfl_down_sync(0xffffffffu, local, o);
        if (lane == 0) s_red[wid][0] = local;
        __syncthreads();
        if (tid == 0) {
            float bs = 0.f;
            #pragma unroll
            for (int w = 0; w < NWARP; w++) bs += s_red[w][0];
            atomicAdd(&g_S0, bs);                 // ONE REDG.F32 per block
            block_ticket(out);                    // ONE ticket per block
        }
    } else {
        // ========== sparse: one block per batch (R14-proven) ==========
        const int b = bid;
        float a0 = 0.f, a1 = 0.f, a2 = 0.f, a3 = 0.f, a4 = 0.f, a5 = 0.f, a6 = 0.f;
        float r_fx = 0.f, r_fy = 0.f, r_tw = 0.f, r_th = 0.f;
        int   r_label = 0;

        for (int i = tid; i < HASH_SZ; i += TPB) s_hash[i] = -1;
        if (tid < TT) s_loser[tid] = 0;
        if (tid < 2)  s_cnt[tid] = 0;
        if (tid < 2*NA) s_anchor[tid] = anchors[tid];
        __syncthreads();

        // phase 0: one thread per target
        if (tid < TT) {
            const int t = b * TT + tid;
            const float* r = tg + (size_t)t * 5;
            float r0 = r[0], r1 = r[1], r2 = r[2], r3 = r[3], r4 = r[4];
            int valid = ((r0 + r1 + r2 + r3 + r4) != 0.f);
            float gx = r1 * NW, gy = r2 * NH, gw = r3 * NW, gh = r4 * NH;
            int gi = (int)floorf(gx), gj = (int)floorf(gy);
            float bestIou = -1.f; int best = 0; float awb = 1.f, ahb = 1.f;
            #pragma unroll
            for (int a = 0; a < NA; a++) {
                float aw = s_anchor[2*a], ah = s_anchor[2*a+1];
                float inter = fminf(gw, aw) * fminf(gh, ah);
                float iou   = inter / (gw * gh + aw * ah - inter);
                if (iou > bestIou) { bestIou = iou; best = a; awb = aw; ahb = ah; }
            }
            s_meta[tid] = (valid << 28) | (best << 16) | (gj << 8) | gi;
            s_gw[tid] = gw; s_gh[tid] = gh;
            r_label = (int)r0;
            r_fx = gx - floorf(gx);
            r_fy = gy - floorf(gy);
            r_tw = __logf(gw / awb + 1e-16f);
            r_th = __logf(gh / ahb + 1e-16f);
        }
        __syncthreads();

        // phase 0.5: last-write-wins within this batch (2500 pairs)
        for (int p = tid; p < TT*TT; p += TPB) {
            int ti = p / TT, tj = p - (p / TT) * TT;
            if (tj > ti) {
                int m1 = s_meta[ti];
                if ((m1 >> 28) && m1 == s_meta[tj]) s_loser[ti] = 1;   // benign race
            }
        }
        __syncthreads();

        // phase 1+2 merged: union correction is order-free (same -bce0 either way)
        if (tid < TT) {
            int meta = s_meta[tid];
            if ((meta >> 28) && !s_loser[tid]) {
                int best = (meta >> 16) & 0xff, gj = (meta >> 8) & 0xff, gi = meta & 0xff;
                int cell = ((b * NA + best) * NH + gj) * NW + gi;
                unsigned h = hash_cell(cell);
                bool mine = false;
                while (true) {
                    int prev = atomicCAS(&s_hash[h], -1, cell);
                    if (prev == -1)   { mine = true; break; }
                    if (prev == cell) break;
                    h = (h + 1) & HASH_MASK;
                }
                atomicAdd(&s_cnt[0], 1);

                const float* bp = x + (size_t)(b * NA + best) * ATTRS * NHW
                                    + (size_t)gj * NW + gi;
                float x0 = bp[0];
                float x1 = bp[(size_t)NHW];
                float x2 = bp[2 * (size_t)NHW];
                float x3 = bp[3 * (size_t)NHW];
                float xc = bp[6 * (size_t)NHW];
                float sv[NC];
                #pragma unroll
                for (int c = 0; c < NC; c++) sv[c] = bp[(size_t)(7 + c) * NHW];

                float dx = sigf(x0) - r_fx;
                float dy = sigf(x1) - r_fy;
                float dw = x2 - r_tw;
                float dh = x3 - r_th;
                a2 += dx * dx;
                a3 += dy * dy;
                a4 += dw * dw;
                a5 += dh * dh;
                a1 += sp_fast(-xc);
                if (mine) { a0 -= sp_fast(xc); atomicAdd(&s_cnt[1], 1); }

                float m = -1e30f;
                #pragma unroll
                for (int c = 0; c < NC; c++) { sv[c] = sigf(sv[c]); m = fmaxf(m, sv[c]); }
                float sum = 0.f;
                #pragma unroll
                for (int c = 0; c < NC; c++) sum += __expf(sv[c] - m);
                a6 += m + __logf(sum) - sv[r_label];
            }
        }
        if (tid < TT * NA) {                        // 250 ignore candidates
            int tl = tid / NA, a = tid - (tid / NA) * NA;
            int meta = s_meta[tl];
            if (meta >> 28) {
                float gw = s_gw[tl], gh = s_gh[tl];
                float aw = s_anchor[2*a], ah = s_anchor[2*a+1];
                float inter = fminf(gw, aw) * fminf(gh, ah);
                float iou   = inter / (gw * gh + aw * ah - inter);
                if (iou > 0.6f) {
                    int gj = (meta >> 8) & 0xff, gi = meta & 0xff;
                    int cell = ((b * NA + a) * NH + gj) * NW + gi;
                    unsigned h = hash_cell(cell);
                    bool mine = false;
                    while (true) {
                        int prev = atomicCAS(&s_hash[h], -1, cell);
                        if (prev == -1)   { mine = true; break; }
                        if (prev == cell) break;       // claimed (obj or dup)
                        h = (h + 1) & HASH_MASK;
                    }
                    if (mine) {
                        atomicAdd(&s_cnt[1], 1);
                        float xc = x[((size_t)(b * NA + a) * ATTRS + 6) * NHW
                                     + (size_t)gj * NW + gi];
                        a0 -= sp_fast(xc);
                    }
                }
            }
        }

        // block reduction -> global accumulators (one atomic set per block)
        #pragma unroll
        for (int o = 16; o; o >>= 1) {
            a0 += __shfl_down_sync(0xffffffffu, a0, o);
            a1 += __shfl_down_sync(0xffffffffu, a1, o);
            a2 += __shfl_down_sync(0xffffffffu, a2, o);
            a3 += __shfl_down_sync(0xffffffffu, a3, o);
            a4 += __shfl_down_sync(0xffffffffu, a4, o);
            a5 += __shfl_down_sync(0xffffffffu, a5, o);
            a6 += __shfl_down_sync(0xffffffffu, a6, o);
        }
        if (lane == 0) {
            s_red[wid][0] = a0; s_red[wid][1] = a1; s_red[wid][2] = a2;
            s_red[wid][3] = a3; s_red[wid][4] = a4; s_red[wid][5] = a5;
            s_red[wid][6] = a6;
        }
        __syncthreads();
        if (tid == 0) {
            float c[7] = {0,0,0,0,0,0,0};
            #pragma unroll
            for (int w = 0; w < NWARP; w++)
                #pragma unroll
                for (int i = 0; i < 7; i++) c[i] += s_red[w][i];
            #pragma unroll
            for (int i = 0; i < 7; i++) atomicAdd(&g_crA[i], c[i]);
            atomicAdd(&g_nObjG, s_cnt[0]);
            atomicAdd(&g_removedG, s_cnt[1]);
            block_ticket(out);
        }
    }
}

extern "C" void kernel_launch(void* const* d_in, const int* in_sizes, int n_in,
                              void* d_out, int out_size) {
    const float* x  = (const float*)d_in[0];
    const float* tg = (const float*)d_in[1];
    const float* an = (const float*)d_in[2];
    fused<<<NB_TOTAL, TPB>>>(x, tg, an, (float*)d_out);
}